// round 1
// baseline (speedup 1.0000x reference)
#include <cuda_runtime.h>
#include <cuda_bf16.h>

#define NN 100000
#define DD 128
#define BM 64          // nodes per block in layer kernel
#define XSTRIDE 260    // padded row stride (floats) for x tile, avoids bank conflicts

// ---------------- scratch (no allocations allowed) ----------------
__device__ float g_agg[(size_t)NN * DD];
__device__ float g_h1 [(size_t)NN * DD];
__device__ float g_deg[NN];
__device__ float g_inv[NN];

// ---------------- packed f32x2 helpers ----------------
#define FMA2(d, a, b) asm("fma.rn.f32x2 %0, %1, %2, %0;" : "+l"(d) : "l"(a), "l"(b))
#define PACKDUP(d, f) asm("mov.b64 %0, {%1, %1};" : "=l"(d) : "f"(f))
#define UNPACK2(lo, hi, p) asm("mov.b64 {%0, %1}, %2;" : "=f"(lo), "=f"(hi) : "l"(p))

// ---------------- kernels ----------------
__global__ void zero_kernel(float4* __restrict__ p, int n4) {
    int i = blockIdx.x * blockDim.x + threadIdx.x;
    if (i < n4) p[i] = make_float4(0.f, 0.f, 0.f, 0.f);
}

__global__ void deg_kernel(const int* __restrict__ dst, float* __restrict__ deg, int E) {
    int e = blockIdx.x * blockDim.x + threadIdx.x;
    if (e < E) atomicAdd(&deg[dst[e]], 1.0f);
}

__global__ void inv_kernel(const float* __restrict__ deg, float* __restrict__ inv) {
    int i = blockIdx.x * blockDim.x + threadIdx.x;
    if (i < NN) inv[i] = 1.0f / fmaxf(deg[i], 1.0f);
}

// warp per edge: each lane moves one float4 (16B) of the 512B feature row
__global__ void scatter_kernel(const float* __restrict__ x,
                               const int* __restrict__ src,
                               const int* __restrict__ dst,
                               float* __restrict__ agg, int E) {
    int gid = blockIdx.x * blockDim.x + threadIdx.x;
    int e = gid >> 5;
    if (e >= E) return;
    int lane = gid & 31;
    int s = __ldg(&src[e]);
    int d = __ldg(&dst[e]);
    float4 v = __ldg(((const float4*)x) + (size_t)s * 32 + lane);
    float* ap = agg + (size_t)d * 128 + lane * 4;
    atomicAdd(ap + 0, v.x);
    atomicAdd(ap + 1, v.y);
    atomicAdd(ap + 2, v.z);
    atomicAdd(ap + 3, v.w);
}

// out[n] = relu?( x[n] @ Ws + (agg[n]*inv[n]) @ Wn + b )
// fused as one K=256 GEMM: input row [x | mean], W stacked [Ws; Wn]
__global__ __launch_bounds__(256) void layer_kernel(
    const float* __restrict__ x,      // [N,128]
    const float* __restrict__ agg,    // [N,128]
    const float* __restrict__ invdeg, // [N]
    const float* __restrict__ Ws,     // [128,128] row-major (k, j)
    const float* __restrict__ Wn,     // [128,128]
    const float* __restrict__ bias,   // [128]
    float* __restrict__ out,          // [N,128]
    int do_relu)
{
    extern __shared__ float smem[];
    float* wsm = smem;                 // [256][128]  (k-major) = 131072 B
    float* xsm = smem + 256 * 128;     // [BM][XSTRIDE] = 66560 B
    const int t = threadIdx.x;
    const int base = blockIdx.x * BM;

    // --- stage W (both matrices) ---
    {
        float4* w4 = (float4*)wsm;
        const float4* Ws4 = (const float4*)Ws;
        const float4* Wn4 = (const float4*)Wn;
        #pragma unroll
        for (int i = t; i < 8192; i += 256)
            w4[i] = (i < 4096) ? __ldg(&Ws4[i]) : __ldg(&Wn4[i - 4096]);
    }

    // --- stage input tile: [x row | mean row] per node ---
    for (int i = t; i < BM * 32; i += 256) {
        int n = i >> 5, k4 = i & 31;
        int node = base + n;
        float4 vx = make_float4(0.f, 0.f, 0.f, 0.f);
        float4 va = vx;
        if (node < NN) {
            vx = __ldg(((const float4*)x) + (size_t)node * 32 + k4);
            float iv = __ldg(&invdeg[node]);
            float4 a = __ldg(((const float4*)agg) + (size_t)node * 32 + k4);
            va = make_float4(a.x * iv, a.y * iv, a.z * iv, a.w * iv);
        }
        float4* row = (float4*)&xsm[n * XSTRIDE];
        row[k4] = vx;
        row[32 + k4] = va;
    }
    __syncthreads();

    // --- register-blocked compute: 4 nodes x 8 cols per thread ---
    const int c8 = (t & 15) * 8;        // column strip
    const int n0 = (t >> 4) * 4;        // node strip
    unsigned long long acc[4][4];
    #pragma unroll
    for (int i = 0; i < 4; i++)
        #pragma unroll
        for (int j = 0; j < 4; j++) acc[i][j] = 0ull;

    const float* xr = &xsm[n0 * XSTRIDE];
    #pragma unroll 4
    for (int k = 0; k < 256; k++) {
        float a0 = xr[k];
        float a1 = xr[XSTRIDE + k];
        float a2 = xr[2 * XSTRIDE + k];
        float a3 = xr[3 * XSTRIDE + k];
        unsigned long long p0, p1, p2, p3;
        PACKDUP(p0, a0); PACKDUP(p1, a1); PACKDUP(p2, a2); PACKDUP(p3, a3);
        const ulonglong2* wq = (const ulonglong2*)&wsm[k * 128 + c8];
        ulonglong2 wa = wq[0];
        ulonglong2 wb = wq[1];
        FMA2(acc[0][0], p0, wa.x); FMA2(acc[0][1], p0, wa.y);
        FMA2(acc[0][2], p0, wb.x); FMA2(acc[0][3], p0, wb.y);
        FMA2(acc[1][0], p1, wa.x); FMA2(acc[1][1], p1, wa.y);
        FMA2(acc[1][2], p1, wb.x); FMA2(acc[1][3], p1, wb.y);
        FMA2(acc[2][0], p2, wa.x); FMA2(acc[2][1], p2, wa.y);
        FMA2(acc[2][2], p2, wb.x); FMA2(acc[2][3], p2, wb.y);
        FMA2(acc[3][0], p3, wa.x); FMA2(acc[3][1], p3, wa.y);
        FMA2(acc[3][2], p3, wb.x); FMA2(acc[3][3], p3, wb.y);
    }

    // --- epilogue: bias (+relu), store ---
    const float4* b4 = (const float4*)bias;
    float4 bv0 = __ldg(&b4[c8 / 4]);
    float4 bv1 = __ldg(&b4[c8 / 4 + 1]);
    #pragma unroll
    for (int i = 0; i < 4; i++) {
        int node = base + n0 + i;
        if (node >= NN) break;
        float e0, e1, e2, e3, e4, e5, e6, e7;
        UNPACK2(e0, e1, acc[i][0]);
        UNPACK2(e2, e3, acc[i][1]);
        UNPACK2(e4, e5, acc[i][2]);
        UNPACK2(e6, e7, acc[i][3]);
        float4 o0 = make_float4(e0 + bv0.x, e1 + bv0.y, e2 + bv0.z, e3 + bv0.w);
        float4 o1 = make_float4(e4 + bv1.x, e5 + bv1.y, e6 + bv1.z, e7 + bv1.w);
        if (do_relu) {
            o0.x = fmaxf(o0.x, 0.f); o0.y = fmaxf(o0.y, 0.f);
            o0.z = fmaxf(o0.z, 0.f); o0.w = fmaxf(o0.w, 0.f);
            o1.x = fmaxf(o1.x, 0.f); o1.y = fmaxf(o1.y, 0.f);
            o1.z = fmaxf(o1.z, 0.f); o1.w = fmaxf(o1.w, 0.f);
        }
        float4* op = ((float4*)out) + (size_t)node * 32 + c8 / 4;
        op[0] = o0;
        op[1] = o1;
    }
}

// ---------------- launch ----------------
extern "C" void kernel_launch(void* const* d_in, const int* in_sizes, int n_in,
                              void* d_out, int out_size) {
    const float* in_feat  = (const float*)d_in[0];
    const float* W1_self  = (const float*)d_in[1];
    const float* W1_neigh = (const float*)d_in[2];
    const float* b1       = (const float*)d_in[3];
    const float* W2_self  = (const float*)d_in[4];
    const float* W2_neigh = (const float*)d_in[5];
    const float* b2       = (const float*)d_in[6];
    const int*   src      = (const int*)d_in[7];
    const int*   dst      = (const int*)d_in[8];
    const int E = in_sizes[7];

    float* out = (float*)d_out;

    float *agg, *h1, *deg, *inv;
    cudaGetSymbolAddress((void**)&agg, g_agg);
    cudaGetSymbolAddress((void**)&h1,  g_h1);
    cudaGetSymbolAddress((void**)&deg, g_deg);
    cudaGetSymbolAddress((void**)&inv, g_inv);

    const int smem_bytes = 256 * 128 * 4 + BM * XSTRIDE * 4;  // 197632
    cudaFuncSetAttribute(layer_kernel, cudaFuncAttributeMaxDynamicSharedMemorySize, smem_bytes);

    const int agg4 = NN * DD / 4;          // 3.2M float4
    const int deg4 = NN / 4;               // 25k float4
    const int zb_agg = (agg4 + 255) / 256;
    const int zb_deg = (deg4 + 255) / 256;
    const int eb     = (E + 255) / 256;
    const int sb     = (int)(((long long)E * 32 + 255) / 256);
    const int nb     = (NN + 255) / 256;
    const int lb     = (NN + BM - 1) / BM;

    // degree (shared by both layers)
    zero_kernel<<<zb_deg, 256>>>((float4*)deg, deg4);
    deg_kernel<<<eb, 256>>>(dst, deg, E);
    inv_kernel<<<nb, 256>>>(deg, inv);

    // ---- layer 1 ----
    zero_kernel<<<zb_agg, 256>>>((float4*)agg, agg4);
    scatter_kernel<<<sb, 256>>>(in_feat, src, dst, agg, E);
    layer_kernel<<<lb, 256, smem_bytes>>>(in_feat, agg, inv, W1_self, W1_neigh, b1, h1, 1);

    // ---- layer 2 ----
    zero_kernel<<<zb_agg, 256>>>((float4*)agg, agg4);
    scatter_kernel<<<sb, 256>>>(h1, src, dst, agg, E);
    layer_kernel<<<lb, 256, smem_bytes>>>(h1, agg, inv, W2_self, W2_neigh, b2, out, 0);
}

// round 2
// speedup vs baseline: 1.3609x; 1.3609x over previous
#include <cuda_runtime.h>
#include <cuda_bf16.h>

#define NN 100000
#define EE 1600000
#define DD 128
#define BM 64          // nodes per block in layer kernel
#define XSTRIDE 260    // padded row stride (floats) for x tile
#define SCAN_T 1024
#define CHUNK  98      // ceil(NN / SCAN_T)

// ---------------- scratch (no allocations allowed) ----------------
__device__ float g_h1 [(size_t)NN * DD];
__device__ int   g_cnt[NN];
__device__ int   g_off[NN + 1];
__device__ int   g_cur[NN];
__device__ int   g_csr[EE];

// ---------------- packed f32x2 helpers ----------------
#define FMA2(d, a, b) asm("fma.rn.f32x2 %0, %1, %2, %0;" : "+l"(d) : "l"(a), "l"(b))
#define PACKDUP(d, f) asm("mov.b64 %0, {%1, %1};" : "=l"(d) : "f"(f))
#define UNPACK2(lo, hi, p) asm("mov.b64 {%0, %1}, %2;" : "=f"(lo), "=f"(hi) : "l"(p))

// ---------------- CSR build ----------------
__global__ void zero_cnt_kernel(int* __restrict__ cnt) {
    int i = blockIdx.x * blockDim.x + threadIdx.x;
    if (i < NN) cnt[i] = 0;
}

__global__ void hist_kernel(const int* __restrict__ dst, int* __restrict__ cnt, int E) {
    int e = blockIdx.x * blockDim.x + threadIdx.x;
    if (e < E) atomicAdd(&cnt[dst[e]], 1);
}

// single-block exclusive scan: off[i] = sum cnt[0..i), also copies to cur
__global__ __launch_bounds__(SCAN_T) void scan_kernel(const int* __restrict__ cnt,
                                                      int* __restrict__ off,
                                                      int* __restrict__ cur) {
    __shared__ int ssum[SCAN_T];
    int t = threadIdx.x;
    int start = t * CHUNK;
    int s = 0;
    for (int i = 0; i < CHUNK; i++) {
        int idx = start + i;
        if (idx < NN) s += cnt[idx];
    }
    ssum[t] = s;
    __syncthreads();
    for (int d = 1; d < SCAN_T; d <<= 1) {
        int v = (t >= d) ? ssum[t - d] : 0;
        __syncthreads();
        ssum[t] += v;
        __syncthreads();
    }
    int running = (t == 0) ? 0 : ssum[t - 1];
    for (int i = 0; i < CHUNK; i++) {
        int idx = start + i;
        if (idx < NN) {
            off[idx] = running;
            cur[idx] = running;
            running += cnt[idx];
        }
    }
    if (t == SCAN_T - 1) off[NN] = running;
}

__global__ void fill_kernel(const int* __restrict__ src, const int* __restrict__ dst,
                            int* __restrict__ cur, int* __restrict__ csr, int E) {
    int e = blockIdx.x * blockDim.x + threadIdx.x;
    if (e < E) {
        int pos = atomicAdd(&cur[dst[e]], 1);
        csr[pos] = src[e];
    }
}

// ---------------- fused gather + GEMM layer ----------------
// out[n] = relu?( x[n] @ Ws + mean_{s in N(n)} x[s] @ Wn + b )
// one K=256 GEMM on [x | mean] with stacked [Ws; Wn]
__global__ __launch_bounds__(256) void layer_kernel(
    const float* __restrict__ x,      // [N,128]
    const int* __restrict__ off,      // [N+1]
    const int* __restrict__ csr,      // [E] src sorted by dst
    const float* __restrict__ Ws,     // [128,128] row-major (k, j)
    const float* __restrict__ Wn,     // [128,128]
    const float* __restrict__ bias,   // [128]
    float* __restrict__ out,          // [N,128]
    int do_relu)
{
    extern __shared__ float smem[];
    float* wsm = smem;                 // [256][128] k-major = 131072 B
    float* xsm = smem + 256 * 128;     // [BM][XSTRIDE] = 66560 B
    const int t = threadIdx.x;
    const int base = blockIdx.x * BM;
    const int w = t >> 5, lane = t & 31;
    const float4* x4 = (const float4*)x;

    // --- stage W (both matrices, stacked along k) ---
    {
        float4* w4 = (float4*)wsm;
        const float4* Ws4 = (const float4*)Ws;
        const float4* Wn4 = (const float4*)Wn;
        #pragma unroll
        for (int i = t; i < 8192; i += 256)
            w4[i] = (i < 4096) ? __ldg(&Ws4[i]) : __ldg(&Wn4[i - 4096]);
    }

    // --- gather: warp per node, 8 nodes per warp; lane owns one float4 slice ---
    #pragma unroll 1
    for (int i = 0; i < BM / 8; i++) {
        int r = w * 8 + i;              // row within tile
        int node = base + r;
        float4 acc = make_float4(0.f, 0.f, 0.f, 0.f);
        int beg = 0, end = 0;
        if (node < NN) { beg = __ldg(&off[node]); end = __ldg(&off[node + 1]); }
        int j = beg;
        for (; j + 3 < end; j += 4) {
            int s0 = __ldg(&csr[j]);
            int s1 = __ldg(&csr[j + 1]);
            int s2 = __ldg(&csr[j + 2]);
            int s3 = __ldg(&csr[j + 3]);
            float4 v0 = __ldg(&x4[(size_t)s0 * 32 + lane]);
            float4 v1 = __ldg(&x4[(size_t)s1 * 32 + lane]);
            float4 v2 = __ldg(&x4[(size_t)s2 * 32 + lane]);
            float4 v3 = __ldg(&x4[(size_t)s3 * 32 + lane]);
            acc.x += v0.x + v1.x + v2.x + v3.x;
            acc.y += v0.y + v1.y + v2.y + v3.y;
            acc.z += v0.z + v1.z + v2.z + v3.z;
            acc.w += v0.w + v1.w + v2.w + v3.w;
        }
        for (; j < end; j++) {
            int s = __ldg(&csr[j]);
            float4 v = __ldg(&x4[(size_t)s * 32 + lane]);
            acc.x += v.x; acc.y += v.y; acc.z += v.z; acc.w += v.w;
        }
        float inv = 1.0f / fmaxf((float)(end - beg), 1.0f);
        float4 vx = make_float4(0.f, 0.f, 0.f, 0.f);
        if (node < NN) vx = __ldg(&x4[(size_t)node * 32 + lane]);
        float4* row = (float4*)&xsm[r * XSTRIDE];
        row[lane] = vx;
        row[32 + lane] = make_float4(acc.x * inv, acc.y * inv, acc.z * inv, acc.w * inv);
    }
    __syncthreads();

    // --- register-blocked compute: 4 nodes x 8 cols per thread ---
    const int c8 = (t & 15) * 8;
    const int n0 = (t >> 4) * 4;
    unsigned long long acc[4][4];
    #pragma unroll
    for (int i = 0; i < 4; i++)
        #pragma unroll
        for (int jj = 0; jj < 4; jj++) acc[i][jj] = 0ull;

    const float* xr = &xsm[n0 * XSTRIDE];
    #pragma unroll 4
    for (int k = 0; k < 256; k++) {
        float a0 = xr[k];
        float a1 = xr[XSTRIDE + k];
        float a2 = xr[2 * XSTRIDE + k];
        float a3 = xr[3 * XSTRIDE + k];
        unsigned long long p0, p1, p2, p3;
        PACKDUP(p0, a0); PACKDUP(p1, a1); PACKDUP(p2, a2); PACKDUP(p3, a3);
        const ulonglong2* wq = (const ulonglong2*)&wsm[k * 128 + c8];
        ulonglong2 wa = wq[0];
        ulonglong2 wb = wq[1];
        FMA2(acc[0][0], p0, wa.x); FMA2(acc[0][1], p0, wa.y);
        FMA2(acc[0][2], p0, wb.x); FMA2(acc[0][3], p0, wb.y);
        FMA2(acc[1][0], p1, wa.x); FMA2(acc[1][1], p1, wa.y);
        FMA2(acc[1][2], p1, wb.x); FMA2(acc[1][3], p1, wb.y);
        FMA2(acc[2][0], p2, wa.x); FMA2(acc[2][1], p2, wa.y);
        FMA2(acc[2][2], p2, wb.x); FMA2(acc[2][3], p2, wb.y);
        FMA2(acc[3][0], p3, wa.x); FMA2(acc[3][1], p3, wa.y);
        FMA2(acc[3][2], p3, wb.x); FMA2(acc[3][3], p3, wb.y);
    }

    // --- epilogue: bias (+relu), store ---
    const float4* b4 = (const float4*)bias;
    float4 bv0 = __ldg(&b4[c8 / 4]);
    float4 bv1 = __ldg(&b4[c8 / 4 + 1]);
    #pragma unroll
    for (int i = 0; i < 4; i++) {
        int node = base + n0 + i;
        if (node >= NN) break;
        float e0, e1, e2, e3, e4, e5, e6, e7;
        UNPACK2(e0, e1, acc[i][0]);
        UNPACK2(e2, e3, acc[i][1]);
        UNPACK2(e4, e5, acc[i][2]);
        UNPACK2(e6, e7, acc[i][3]);
        float4 o0 = make_float4(e0 + bv0.x, e1 + bv0.y, e2 + bv0.z, e3 + bv0.w);
        float4 o1 = make_float4(e4 + bv1.x, e5 + bv1.y, e6 + bv1.z, e7 + bv1.w);
        if (do_relu) {
            o0.x = fmaxf(o0.x, 0.f); o0.y = fmaxf(o0.y, 0.f);
            o0.z = fmaxf(o0.z, 0.f); o0.w = fmaxf(o0.w, 0.f);
            o1.x = fmaxf(o1.x, 0.f); o1.y = fmaxf(o1.y, 0.f);
            o1.z = fmaxf(o1.z, 0.f); o1.w = fmaxf(o1.w, 0.f);
        }
        float4* op = ((float4*)out) + (size_t)node * 32 + c8 / 4;
        op[0] = o0;
        op[1] = o1;
    }
}

// ---------------- launch ----------------
extern "C" void kernel_launch(void* const* d_in, const int* in_sizes, int n_in,
                              void* d_out, int out_size) {
    const float* in_feat  = (const float*)d_in[0];
    const float* W1_self  = (const float*)d_in[1];
    const float* W1_neigh = (const float*)d_in[2];
    const float* b1       = (const float*)d_in[3];
    const float* W2_self  = (const float*)d_in[4];
    const float* W2_neigh = (const float*)d_in[5];
    const float* b2       = (const float*)d_in[6];
    const int*   src      = (const int*)d_in[7];
    const int*   dst      = (const int*)d_in[8];
    const int E = in_sizes[7];

    float* out = (float*)d_out;

    float *h1;
    int *cnt, *off, *cur, *csr;
    cudaGetSymbolAddress((void**)&h1,  g_h1);
    cudaGetSymbolAddress((void**)&cnt, g_cnt);
    cudaGetSymbolAddress((void**)&off, g_off);
    cudaGetSymbolAddress((void**)&cur, g_cur);
    cudaGetSymbolAddress((void**)&csr, g_csr);

    const int smem_bytes = 256 * 128 * 4 + BM * XSTRIDE * 4;  // 197632
    cudaFuncSetAttribute(layer_kernel, cudaFuncAttributeMaxDynamicSharedMemorySize, smem_bytes);

    const int nb = (NN + 255) / 256;
    const int eb = (E + 255) / 256;
    const int lb = (NN + BM - 1) / BM;

    // ---- CSR build (by dst) ----
    zero_cnt_kernel<<<nb, 256>>>(cnt);
    hist_kernel<<<eb, 256>>>(dst, cnt, E);
    scan_kernel<<<1, SCAN_T>>>(cnt, off, cur);
    fill_kernel<<<eb, 256>>>(src, dst, cur, csr, E);

    // ---- layers (gather fused into GEMM) ----
    layer_kernel<<<lb, 256, smem_bytes>>>(in_feat, off, csr, W1_self, W1_neigh, b1, h1, 1);
    layer_kernel<<<lb, 256, smem_bytes>>>(h1, off, csr, W2_self, W2_neigh, b2, out, 0);
}

// round 3
// speedup vs baseline: 1.7488x; 1.2851x over previous
#include <cuda_runtime.h>
#include <cuda_bf16.h>

#define NN 100000
#define EE 1600000
#define DD 128
#define BM 64          // nodes per block in layer kernel
#define XSTRIDE 260    // padded row stride (floats) for x tile
#define SCAN_T 1024
#define CHUNK  98      // ceil(NN / SCAN_T)

// ---------------- scratch (no allocations allowed) ----------------
__device__ float g_h1 [(size_t)NN * DD];
__device__ float g_agg[(size_t)NN * DD];
__device__ int   g_cnt[NN];
__device__ int   g_off[NN + 1];
__device__ int   g_cur[NN];
__device__ int   g_csr[EE];

// ---------------- packed f32x2 helpers ----------------
#define FMA2(d, a, b) asm("fma.rn.f32x2 %0, %1, %2, %0;" : "+l"(d) : "l"(a), "l"(b))
#define PACKDUP(d, f) asm("mov.b64 %0, {%1, %1};" : "=l"(d) : "f"(f))
#define UNPACK2(lo, hi, p) asm("mov.b64 {%0, %1}, %2;" : "=f"(lo), "=f"(hi) : "l"(p))

// ---------------- CSR build ----------------
__global__ void zero_cnt_kernel(int* __restrict__ cnt) {
    int i = blockIdx.x * blockDim.x + threadIdx.x;
    if (i < NN) cnt[i] = 0;
}

__global__ void hist_kernel(const int* __restrict__ dst, int* __restrict__ cnt, int E) {
    int e = blockIdx.x * blockDim.x + threadIdx.x;
    if (e < E) atomicAdd(&cnt[dst[e]], 1);
}

// single-block exclusive scan
__global__ __launch_bounds__(SCAN_T) void scan_kernel(const int* __restrict__ cnt,
                                                      int* __restrict__ off,
                                                      int* __restrict__ cur) {
    __shared__ int ssum[SCAN_T];
    int t = threadIdx.x;
    int start = t * CHUNK;
    int s = 0;
    for (int i = 0; i < CHUNK; i++) {
        int idx = start + i;
        if (idx < NN) s += cnt[idx];
    }
    ssum[t] = s;
    __syncthreads();
    for (int d = 1; d < SCAN_T; d <<= 1) {
        int v = (t >= d) ? ssum[t - d] : 0;
        __syncthreads();
        ssum[t] += v;
        __syncthreads();
    }
    int running = (t == 0) ? 0 : ssum[t - 1];
    for (int i = 0; i < CHUNK; i++) {
        int idx = start + i;
        if (idx < NN) {
            off[idx] = running;
            cur[idx] = running;
            running += cnt[idx];
        }
    }
    if (t == SCAN_T - 1) off[NN] = running;
}

__global__ void fill_kernel(const int* __restrict__ src, const int* __restrict__ dst,
                            int* __restrict__ cur, int* __restrict__ csr, int E) {
    int e = blockIdx.x * blockDim.x + threadIdx.x;
    if (e < E) {
        int pos = atomicAdd(&cur[dst[e]], 1);
        csr[pos] = src[e];
    }
}

// ---------------- mean gather: warp per node, shfl-broadcast indices ----------------
__global__ __launch_bounds__(256) void gather_kernel(
    const float* __restrict__ x,     // [N,128]
    const int* __restrict__ off,     // [N+1]
    const int* __restrict__ csr,     // [E]
    float* __restrict__ agg)         // [N,128] <- mean
{
    int gw = (blockIdx.x * blockDim.x + threadIdx.x) >> 5;   // node id
    if (gw >= NN) return;
    int lane = threadIdx.x & 31;
    int beg = __ldg(&off[gw]);
    int end = __ldg(&off[gw + 1]);
    const float4* x4 = (const float4*)x;

    float4 acc = make_float4(0.f, 0.f, 0.f, 0.f);
    int j = beg;
    while (j < end) {
        int cnt = min(end - j, 32);
        int idx = (lane < cnt) ? __ldg(&csr[j + lane]) : 0;
        int m = 0;
        #pragma unroll 1
        for (; m + 8 <= cnt; m += 8) {
            int s0 = __shfl_sync(0xffffffffu, idx, m + 0);
            int s1 = __shfl_sync(0xffffffffu, idx, m + 1);
            int s2 = __shfl_sync(0xffffffffu, idx, m + 2);
            int s3 = __shfl_sync(0xffffffffu, idx, m + 3);
            int s4 = __shfl_sync(0xffffffffu, idx, m + 4);
            int s5 = __shfl_sync(0xffffffffu, idx, m + 5);
            int s6 = __shfl_sync(0xffffffffu, idx, m + 6);
            int s7 = __shfl_sync(0xffffffffu, idx, m + 7);
            float4 v0 = __ldg(&x4[(size_t)s0 * 32 + lane]);
            float4 v1 = __ldg(&x4[(size_t)s1 * 32 + lane]);
            float4 v2 = __ldg(&x4[(size_t)s2 * 32 + lane]);
            float4 v3 = __ldg(&x4[(size_t)s3 * 32 + lane]);
            float4 v4 = __ldg(&x4[(size_t)s4 * 32 + lane]);
            float4 v5 = __ldg(&x4[(size_t)s5 * 32 + lane]);
            float4 v6 = __ldg(&x4[(size_t)s6 * 32 + lane]);
            float4 v7 = __ldg(&x4[(size_t)s7 * 32 + lane]);
            acc.x += (v0.x + v1.x) + (v2.x + v3.x) + (v4.x + v5.x) + (v6.x + v7.x);
            acc.y += (v0.y + v1.y) + (v2.y + v3.y) + (v4.y + v5.y) + (v6.y + v7.y);
            acc.z += (v0.z + v1.z) + (v2.z + v3.z) + (v4.z + v5.z) + (v6.z + v7.z);
            acc.w += (v0.w + v1.w) + (v2.w + v3.w) + (v4.w + v5.w) + (v6.w + v7.w);
        }
        #pragma unroll 1
        for (; m < cnt; m++) {
            int s = __shfl_sync(0xffffffffu, idx, m);
            float4 v = __ldg(&x4[(size_t)s * 32 + lane]);
            acc.x += v.x; acc.y += v.y; acc.z += v.z; acc.w += v.w;
        }
        j += cnt;
    }
    float inv = 1.0f / fmaxf((float)(end - beg), 1.0f);
    ((float4*)agg)[(size_t)gw * 32 + lane] =
        make_float4(acc.x * inv, acc.y * inv, acc.z * inv, acc.w * inv);
}

// ---------------- GEMM layer ----------------
// out[n] = relu?( x[n] @ Ws + mean[n] @ Wn + b )  as K=256 GEMM with stacked W
__global__ __launch_bounds__(256) void layer_kernel(
    const float* __restrict__ x,      // [N,128]
    const float* __restrict__ agg,    // [N,128] (mean)
    const float* __restrict__ Ws,     // [128,128] row-major (k, j)
    const float* __restrict__ Wn,     // [128,128]
    const float* __restrict__ bias,   // [128]
    float* __restrict__ out,          // [N,128]
    int do_relu)
{
    extern __shared__ float smem[];
    float* wsm = smem;                 // [256][128] k-major = 131072 B
    float* xsm = smem + 256 * 128;     // [BM][XSTRIDE] = 66560 B
    const int t = threadIdx.x;
    const int base = blockIdx.x * BM;

    // --- stage W (both matrices, stacked along k) ---
    {
        float4* w4 = (float4*)wsm;
        const float4* Ws4 = (const float4*)Ws;
        const float4* Wn4 = (const float4*)Wn;
        #pragma unroll
        for (int i = t; i < 8192; i += 256)
            w4[i] = (i < 4096) ? __ldg(&Ws4[i]) : __ldg(&Wn4[i - 4096]);
    }

    // --- stage input tile: [x row | mean row] per node ---
    #pragma unroll
    for (int i = t; i < BM * 32; i += 256) {
        int n = i >> 5, k4 = i & 31;
        int node = base + n;
        float4 vx = make_float4(0.f, 0.f, 0.f, 0.f);
        float4 va = vx;
        if (node < NN) {
            vx = __ldg(((const float4*)x) + (size_t)node * 32 + k4);
            va = __ldg(((const float4*)agg) + (size_t)node * 32 + k4);
        }
        float4* row = (float4*)&xsm[n * XSTRIDE];
        row[k4] = vx;
        row[32 + k4] = va;
    }
    __syncthreads();

    // --- register-blocked compute: 4 nodes x 8 cols per thread ---
    const int c8 = (t & 15) * 8;
    const int n0 = (t >> 4) * 4;
    unsigned long long acc[4][4];
    #pragma unroll
    for (int i = 0; i < 4; i++)
        #pragma unroll
        for (int jj = 0; jj < 4; jj++) acc[i][jj] = 0ull;

    const float* xr = &xsm[n0 * XSTRIDE];
    #pragma unroll 4
    for (int k = 0; k < 256; k++) {
        float a0 = xr[k];
        float a1 = xr[XSTRIDE + k];
        float a2 = xr[2 * XSTRIDE + k];
        float a3 = xr[3 * XSTRIDE + k];
        unsigned long long p0, p1, p2, p3;
        PACKDUP(p0, a0); PACKDUP(p1, a1); PACKDUP(p2, a2); PACKDUP(p3, a3);
        const ulonglong2* wq = (const ulonglong2*)&wsm[k * 128 + c8];
        ulonglong2 wa = wq[0];
        ulonglong2 wb = wq[1];
        FMA2(acc[0][0], p0, wa.x); FMA2(acc[0][1], p0, wa.y);
        FMA2(acc[0][2], p0, wb.x); FMA2(acc[0][3], p0, wb.y);
        FMA2(acc[1][0], p1, wa.x); FMA2(acc[1][1], p1, wa.y);
        FMA2(acc[1][2], p1, wb.x); FMA2(acc[1][3], p1, wb.y);
        FMA2(acc[2][0], p2, wa.x); FMA2(acc[2][1], p2, wa.y);
        FMA2(acc[2][2], p2, wb.x); FMA2(acc[2][3], p2, wb.y);
        FMA2(acc[3][0], p3, wa.x); FMA2(acc[3][1], p3, wa.y);
        FMA2(acc[3][2], p3, wb.x); FMA2(acc[3][3], p3, wb.y);
    }

    // --- epilogue: bias (+relu), store ---
    const float4* b4 = (const float4*)bias;
    float4 bv0 = __ldg(&b4[c8 / 4]);
    float4 bv1 = __ldg(&b4[c8 / 4 + 1]);
    #pragma unroll
    for (int i = 0; i < 4; i++) {
        int node = base + n0 + i;
        if (node >= NN) break;
        float e0, e1, e2, e3, e4, e5, e6, e7;
        UNPACK2(e0, e1, acc[i][0]);
        UNPACK2(e2, e3, acc[i][1]);
        UNPACK2(e4, e5, acc[i][2]);
        UNPACK2(e6, e7, acc[i][3]);
        float4 o0 = make_float4(e0 + bv0.x, e1 + bv0.y, e2 + bv0.z, e3 + bv0.w);
        float4 o1 = make_float4(e4 + bv1.x, e5 + bv1.y, e6 + bv1.z, e7 + bv1.w);
        if (do_relu) {
            o0.x = fmaxf(o0.x, 0.f); o0.y = fmaxf(o0.y, 0.f);
            o0.z = fmaxf(o0.z, 0.f); o0.w = fmaxf(o0.w, 0.f);
            o1.x = fmaxf(o1.x, 0.f); o1.y = fmaxf(o1.y, 0.f);
            o1.z = fmaxf(o1.z, 0.f); o1.w = fmaxf(o1.w, 0.f);
        }
        float4* op = ((float4*)out) + (size_t)node * 32 + c8 / 4;
        op[0] = o0;
        op[1] = o1;
    }
}

// ---------------- launch ----------------
extern "C" void kernel_launch(void* const* d_in, const int* in_sizes, int n_in,
                              void* d_out, int out_size) {
    const float* in_feat  = (const float*)d_in[0];
    const float* W1_self  = (const float*)d_in[1];
    const float* W1_neigh = (const float*)d_in[2];
    const float* b1       = (const float*)d_in[3];
    const float* W2_self  = (const float*)d_in[4];
    const float* W2_neigh = (const float*)d_in[5];
    const float* b2       = (const float*)d_in[6];
    const int*   src      = (const int*)d_in[7];
    const int*   dst      = (const int*)d_in[8];
    const int E = in_sizes[7];

    float* out = (float*)d_out;

    float *h1, *agg;
    int *cnt, *off, *cur, *csr;
    cudaGetSymbolAddress((void**)&h1,  g_h1);
    cudaGetSymbolAddress((void**)&agg, g_agg);
    cudaGetSymbolAddress((void**)&cnt, g_cnt);
    cudaGetSymbolAddress((void**)&off, g_off);
    cudaGetSymbolAddress((void**)&cur, g_cur);
    cudaGetSymbolAddress((void**)&csr, g_csr);

    const int smem_bytes = 256 * 128 * 4 + BM * XSTRIDE * 4;  // 197632
    cudaFuncSetAttribute(layer_kernel, cudaFuncAttributeMaxDynamicSharedMemorySize, smem_bytes);

    const int nb = (NN + 255) / 256;
    const int eb = (E + 255) / 256;
    const int gb = (NN * 32 + 255) / 256;   // warp per node
    const int lb = (NN + BM - 1) / BM;

    // ---- CSR build (by dst) ----
    zero_cnt_kernel<<<nb, 256>>>(cnt);
    hist_kernel<<<eb, 256>>>(dst, cnt, E);
    scan_kernel<<<1, SCAN_T>>>(cnt, off, cur);
    fill_kernel<<<eb, 256>>>(src, dst, cur, csr, E);

    // ---- layer 1 ----
    gather_kernel<<<gb, 256>>>(in_feat, off, csr, agg);
    layer_kernel<<<lb, 256, smem_bytes>>>(in_feat, agg, W1_self, W1_neigh, b1, h1, 1);

    // ---- layer 2 ----
    gather_kernel<<<gb, 256>>>(h1, off, csr, agg);
    layer_kernel<<<lb, 256, smem_bytes>>>(h1, agg, W2_self, W2_neigh, b2, out, 0);
}

// round 5
// speedup vs baseline: 2.6965x; 1.5419x over previous
#include <cuda_runtime.h>
#include <cuda_bf16.h>
#include <cstdint>

#define NN 100000
#define EE 1600000
#define DD 128
#define SCAN_T 1024
#define CHUNK  98      // ceil(NN / SCAN_T)

// ---------------- scratch (no allocations allowed) ----------------
__device__ float g_h1 [(size_t)NN * DD];
__device__ float g_agg[(size_t)NN * DD];
__device__ int   g_cnt[NN];
__device__ int   g_off[NN + 1];
__device__ int   g_cur[NN];
__device__ int   g_csr[EE];

// ---------------- CSR build ----------------
__global__ void zero_cnt_kernel(int* __restrict__ cnt) {
    int i = blockIdx.x * blockDim.x + threadIdx.x;
    if (i < NN) cnt[i] = 0;
}

__global__ void hist_kernel(const int* __restrict__ dst, int* __restrict__ cnt, int E) {
    int e = blockIdx.x * blockDim.x + threadIdx.x;
    if (e < E) atomicAdd(&cnt[dst[e]], 1);
}

__global__ __launch_bounds__(SCAN_T) void scan_kernel(const int* __restrict__ cnt,
                                                      int* __restrict__ off,
                                                      int* __restrict__ cur) {
    __shared__ int ssum[SCAN_T];
    int t = threadIdx.x;
    int start = t * CHUNK;
    int s = 0;
    for (int i = 0; i < CHUNK; i++) {
        int idx = start + i;
        if (idx < NN) s += cnt[idx];
    }
    ssum[t] = s;
    __syncthreads();
    for (int d = 1; d < SCAN_T; d <<= 1) {
        int v = (t >= d) ? ssum[t - d] : 0;
        __syncthreads();
        ssum[t] += v;
        __syncthreads();
    }
    int running = (t == 0) ? 0 : ssum[t - 1];
    for (int i = 0; i < CHUNK; i++) {
        int idx = start + i;
        if (idx < NN) {
            off[idx] = running;
            cur[idx] = running;
            running += cnt[idx];
        }
    }
    if (t == SCAN_T - 1) off[NN] = running;
}

__global__ void fill_kernel(const int* __restrict__ src, const int* __restrict__ dst,
                            int* __restrict__ cur, int* __restrict__ csr, int E) {
    int e = blockIdx.x * blockDim.x + threadIdx.x;
    if (e < E) {
        int pos = atomicAdd(&cur[dst[e]], 1);
        csr[pos] = src[e];
    }
}

// ---------------- mean gather: warp per node ----------------
__global__ __launch_bounds__(256) void gather_kernel(
    const float* __restrict__ x,     // [N,128]
    const int* __restrict__ off,     // [N+1]
    const int* __restrict__ csr,     // [E]
    float* __restrict__ agg)         // [N,128] <- mean
{
    int gw = (blockIdx.x * blockDim.x + threadIdx.x) >> 5;   // node id
    if (gw >= NN) return;
    int lane = threadIdx.x & 31;
    int beg = __ldg(&off[gw]);
    int end = __ldg(&off[gw + 1]);
    const float4* x4 = (const float4*)x;

    float4 acc = make_float4(0.f, 0.f, 0.f, 0.f);
    int j = beg;
    int full = beg + ((end - beg) & ~7);
    #pragma unroll 1
    for (; j < full; j += 8) {
        int s0 = __ldg(&csr[j + 0]);
        int s1 = __ldg(&csr[j + 1]);
        int s2 = __ldg(&csr[j + 2]);
        int s3 = __ldg(&csr[j + 3]);
        int s4 = __ldg(&csr[j + 4]);
        int s5 = __ldg(&csr[j + 5]);
        int s6 = __ldg(&csr[j + 6]);
        int s7 = __ldg(&csr[j + 7]);
        float4 v0 = __ldg(&x4[(size_t)s0 * 32 + lane]);
        float4 v1 = __ldg(&x4[(size_t)s1 * 32 + lane]);
        float4 v2 = __ldg(&x4[(size_t)s2 * 32 + lane]);
        float4 v3 = __ldg(&x4[(size_t)s3 * 32 + lane]);
        float4 v4 = __ldg(&x4[(size_t)s4 * 32 + lane]);
        float4 v5 = __ldg(&x4[(size_t)s5 * 32 + lane]);
        float4 v6 = __ldg(&x4[(size_t)s6 * 32 + lane]);
        float4 v7 = __ldg(&x4[(size_t)s7 * 32 + lane]);
        acc.x += (v0.x + v1.x) + (v2.x + v3.x) + (v4.x + v5.x) + (v6.x + v7.x);
        acc.y += (v0.y + v1.y) + (v2.y + v3.y) + (v4.y + v5.y) + (v6.y + v7.y);
        acc.z += (v0.z + v1.z) + (v2.z + v3.z) + (v4.z + v5.z) + (v6.z + v7.z);
        acc.w += (v0.w + v1.w) + (v2.w + v3.w) + (v4.w + v5.w) + (v6.w + v7.w);
    }
    #pragma unroll 1
    for (; j < end; j++) {
        int s = __ldg(&csr[j]);
        float4 v = __ldg(&x4[(size_t)s * 32 + lane]);
        acc.x += v.x; acc.y += v.y; acc.z += v.z; acc.w += v.w;
    }
    float inv = 1.0f / fmaxf((float)(end - beg), 1.0f);
    ((float4*)agg)[(size_t)gw * 32 + lane] =
        make_float4(acc.x * inv, acc.y * inv, acc.z * inv, acc.w * inv);
}

// ======================= tf32 mma.sync GEMM layer =======================
// out[0:N,0:128] = relu?( [x | mean] @ [Ws ; Wn] + b )   (K = 256, tf32)
// Tile: 128 nodes x 128 cols per block, 8 warps in 4x2 (warp: 32 rows x 64 cols).

__device__ __forceinline__ uint32_t f2tf32(float f) {
    uint32_t u;
    asm("cvt.rna.tf32.f32 %0, %1;" : "=r"(u) : "f"(f));
    return u;
}

#define MMA_TF32(c, a, b)                                                        \
    asm volatile("mma.sync.aligned.m16n8k8.row.col.f32.tf32.tf32.f32 "           \
                 "{%0,%1,%2,%3}, {%4,%5,%6,%7}, {%8,%9}, {%0,%1,%2,%3};"         \
                 : "+f"((c)[0]), "+f"((c)[1]), "+f"((c)[2]), "+f"((c)[3])        \
                 : "r"((a)[0]), "r"((a)[1]), "r"((a)[2]), "r"((a)[3]),           \
                   "r"((b)[0]), "r"((b)[1]))

#define ASTRIDE 132   // floats per A row (bank-conflict-free: 132 % 32 == 4)
#define BSTRIDE 260   // floats per B row (260 % 32 == 4), holds k=0..255
#define AS_OFF  128                       // floats (after bias)
#define BS_OFF  (AS_OFF + 128 * ASTRIDE)  // 17024
#define SM_FLOATS (BS_OFF + 128 * BSTRIDE)  // 50304 -> 201216 bytes

__global__ __launch_bounds__(256) void layer_mma_kernel(
    const float* __restrict__ x,     // [N,128] self features
    const float* __restrict__ agg,   // [N,128] mean neighbor features
    const float* __restrict__ Ws,    // [128,128] (k, j) row-major
    const float* __restrict__ Wn,    // [128,128]
    const float* __restrict__ bias,  // [128]
    float* __restrict__ out,         // [N,128]
    int do_relu)
{
    extern __shared__ float smem[];
    float* bsm = smem;                          // [128]
    uint32_t* As = (uint32_t*)(smem + AS_OFF);  // [128][ASTRIDE] tf32
    uint32_t* Bs = (uint32_t*)(smem + BS_OFF);  // [128 n][BSTRIDE] tf32 (k-major)
    const int tid = threadIdx.x;
    const int wid = tid >> 5, lane = tid & 31;
    const int g = lane >> 2, tg = lane & 3;
    const int warp_m = wid & 3, warp_n = wid >> 2;
    const int base = blockIdx.x * 128;

    if (tid < 128) bsm[tid] = __ldg(&bias[tid]);

    // ---- stage B = [Ws ; Wn]^T as Bs[n][k] (tf32) ----
    #pragma unroll 4
    for (int idx = tid; idx < 16384; idx += 256) {
        int k = idx >> 7, n = idx & 127;
        Bs[n * BSTRIDE + k]       = f2tf32(__ldg(&Ws[idx]));
        Bs[n * BSTRIDE + 128 + k] = f2tf32(__ldg(&Wn[idx]));
    }

    float c[2][8][4];
    #pragma unroll
    for (int mt = 0; mt < 2; mt++)
        #pragma unroll
        for (int nt = 0; nt < 8; nt++)
            #pragma unroll
            for (int q = 0; q < 4; q++) c[mt][nt][q] = 0.f;

    // ---- two K-passes: pass0 = x (k 0..127), pass1 = mean (k 128..255) ----
    #pragma unroll 1
    for (int pass = 0; pass < 2; pass++) {
        const float4* src4 = (const float4*)(pass ? agg : x);
        __syncthreads();   // previous-pass readers done before As overwrite
        #pragma unroll 4
        for (int idx = tid; idx < 4096; idx += 256) {
            int r = idx >> 5, k4 = idx & 31;
            int node = base + r;
            float4 v = make_float4(0.f, 0.f, 0.f, 0.f);
            if (node < NN) v = __ldg(&src4[(size_t)node * 32 + k4]);
            uint4 u;
            u.x = f2tf32(v.x); u.y = f2tf32(v.y); u.z = f2tf32(v.z); u.w = f2tf32(v.w);
            *(uint4*)&As[r * ASTRIDE + k4 * 4] = u;
        }
        __syncthreads();

        const uint32_t* ap = &As[(warp_m * 32 + g) * ASTRIDE + tg];
        const uint32_t* bp = &Bs[(warp_n * 64 + g) * BSTRIDE + tg + pass * 128];

        #pragma unroll 4
        for (int ks = 0; ks < 16; ks++) {
            const int kb = ks * 8;
            uint32_t a[2][4];
            #pragma unroll
            for (int mt = 0; mt < 2; mt++) {
                const uint32_t* p = ap + mt * 16 * ASTRIDE + kb;
                a[mt][0] = p[0];
                a[mt][1] = p[8 * ASTRIDE];
                a[mt][2] = p[4];
                a[mt][3] = p[8 * ASTRIDE + 4];
            }
            uint32_t b[8][2];
            #pragma unroll
            for (int nt = 0; nt < 8; nt++) {
                const uint32_t* p = bp + nt * 8 * BSTRIDE + kb;
                b[nt][0] = p[0];
                b[nt][1] = p[4];
            }
            #pragma unroll
            for (int mt = 0; mt < 2; mt++)
                #pragma unroll
                for (int nt = 0; nt < 8; nt++)
                    MMA_TF32(c[mt][nt], a[mt], b[nt]);
        }
    }

    // ---- epilogue: bias (+relu), float2 stores ----
    #pragma unroll
    for (int mt = 0; mt < 2; mt++) {
        #pragma unroll
        for (int half = 0; half < 2; half++) {
            int row = warp_m * 32 + mt * 16 + half * 8 + g;
            int node = base + row;
            if (node < NN) {
                float* orow = out + (size_t)node * 128;
                #pragma unroll
                for (int nt = 0; nt < 8; nt++) {
                    int col = warp_n * 64 + nt * 8 + tg * 2;
                    float v0 = c[mt][nt][half * 2 + 0] + bsm[col];
                    float v1 = c[mt][nt][half * 2 + 1] + bsm[col + 1];
                    if (do_relu) { v0 = fmaxf(v0, 0.f); v1 = fmaxf(v1, 0.f); }
                    *(float2*)(orow + col) = make_float2(v0, v1);
                }
            }
        }
    }
}

// ---------------- launch ----------------
extern "C" void kernel_launch(void* const* d_in, const int* in_sizes, int n_in,
                              void* d_out, int out_size) {
    const float* in_feat  = (const float*)d_in[0];
    const float* W1_self  = (const float*)d_in[1];
    const float* W1_neigh = (const float*)d_in[2];
    const float* b1       = (const float*)d_in[3];
    const float* W2_self  = (const float*)d_in[4];
    const float* W2_neigh = (const float*)d_in[5];
    const float* b2       = (const float*)d_in[6];
    const int*   src      = (const int*)d_in[7];
    const int*   dst      = (const int*)d_in[8];
    const int E = in_sizes[7];

    float* out = (float*)d_out;

    float *h1, *agg;
    int *cnt, *off, *cur, *csr;
    cudaGetSymbolAddress((void**)&h1,  g_h1);
    cudaGetSymbolAddress((void**)&agg, g_agg);
    cudaGetSymbolAddress((void**)&cnt, g_cnt);
    cudaGetSymbolAddress((void**)&off, g_off);
    cudaGetSymbolAddress((void**)&cur, g_cur);
    cudaGetSymbolAddress((void**)&csr, g_csr);

    const int smem_bytes = SM_FLOATS * 4;   // 201216
    cudaFuncSetAttribute(layer_mma_kernel, cudaFuncAttributeMaxDynamicSharedMemorySize, smem_bytes);

    const int nb = (NN + 255) / 256;
    const int eb = (E + 255) / 256;
    const int gb = (NN * 32 + 255) / 256;     // warp per node
    const int lb = (NN + 127) / 128;          // 128-node tiles

    // ---- CSR build (by dst) ----
    zero_cnt_kernel<<<nb, 256>>>(cnt);
    hist_kernel<<<eb, 256>>>(dst, cnt, E);
    scan_kernel<<<1, SCAN_T>>>(cnt, off, cur);
    fill_kernel<<<eb, 256>>>(src, dst, cur, csr, E);

    // ---- layer 1 ----
    gather_kernel<<<gb, 256>>>(in_feat, off, csr, agg);
    layer_mma_kernel<<<lb, 256, smem_bytes>>>(in_feat, agg, W1_self, W1_neigh, b1, h1, 1);

    // ---- layer 2 ----
    gather_kernel<<<gb, 256>>>(h1, off, csr, agg);
    layer_mma_kernel<<<lb, 256, smem_bytes>>>(h1, agg, W2_self, W2_neigh, b2, out, 0);
}